// round 5
// baseline (speedup 1.0000x reference)
#include <cuda_runtime.h>
#include <cstdint>

#define SEQ 2048
#define DK  128

// ---------------- static device scratch (no allocations allowed) ------------
__device__ float g_Pqk[(size_t)SEQ * SEQ];   // P_qk[i][l] = q_i . k_l
__device__ float g_Pvv[(size_t)SEQ * SEQ];   // P_vv[i][l] = v_i . v_l
__device__ float g_U[(size_t)SEQ * DK];      // u_l = Sqq_l k_l (incl 1/(l+1))
// per-step chain constants, 12 floats per step:
// [0..3]={s_l, kqq_l, vv_l, 1/(l+1)}  [4..7]={k1q,k2q,k1u,k2u}
// [8..11]={vl1, vl2, (l)/(l+1), 0}
__device__ float g_chain[(size_t)SEQ * 12];

// ---------------- f32x2 packed helpers (sm_103a) ----------------------------
__device__ __forceinline__ unsigned long long ffma2(unsigned long long a,
                                                    unsigned long long b,
                                                    unsigned long long c) {
    unsigned long long d;
    asm("fma.rn.f32x2 %0, %1, %2, %3;" : "=l"(d) : "l"(a), "l"(b), "l"(c));
    return d;
}
__device__ __forceinline__ unsigned long long fmul2(unsigned long long a,
                                                    unsigned long long b) {
    unsigned long long d;
    asm("mul.rn.f32x2 %0, %1, %2;" : "=l"(d) : "l"(a), "l"(b));
    return d;
}
__device__ __forceinline__ unsigned long long pk2(float lo, float hi) {
    unsigned long long r;
    asm("mov.b64 %0, {%1, %2};" : "=l"(r) : "f"(lo), "f"(hi));
    return r;
}
__device__ __forceinline__ float2 upk2(unsigned long long a) {
    float2 f;
    asm("mov.b64 {%0, %1}, %2;" : "=f"(f.x), "=f"(f.y) : "l"(a));
    return f;
}

// ---------------- Phase 1a: both Gram matrices in one launch ----------------
__global__ void __launch_bounds__(256) k_gemm(const float* __restrict__ q,
                                              const float* __restrict__ kk_,
                                              const float* __restrict__ v) {
    if (blockIdx.y > blockIdx.x) return;
    const float* A; const float* B; float* C;
    if (blockIdx.z == 0) { A = q; B = kk_; C = g_Pqk; }
    else                 { A = v; B = v;   C = g_Pvv; }
    __shared__ float As[32][68];
    __shared__ float Bs[32][68];
    const int tx = threadIdx.x & 15, ty = threadIdx.x >> 4;
    const int i0 = blockIdx.y * 64, l0 = blockIdx.x * 64;
    const int t = threadIdx.x;
    const int r = t >> 2, cc = (t & 3) * 8;
    float acc[4][4] = {};
    for (int k0 = 0; k0 < DK; k0 += 32) {
        float4 a0 = *(const float4*)&A[(size_t)(i0 + r) * DK + k0 + cc];
        float4 a1 = *(const float4*)&A[(size_t)(i0 + r) * DK + k0 + cc + 4];
        float4 b0 = *(const float4*)&B[(size_t)(l0 + r) * DK + k0 + cc];
        float4 b1 = *(const float4*)&B[(size_t)(l0 + r) * DK + k0 + cc + 4];
        __syncthreads();
        As[cc + 0][r] = a0.x; As[cc + 1][r] = a0.y; As[cc + 2][r] = a0.z; As[cc + 3][r] = a0.w;
        As[cc + 4][r] = a1.x; As[cc + 5][r] = a1.y; As[cc + 6][r] = a1.z; As[cc + 7][r] = a1.w;
        Bs[cc + 0][r] = b0.x; Bs[cc + 1][r] = b0.y; Bs[cc + 2][r] = b0.z; Bs[cc + 3][r] = b0.w;
        Bs[cc + 4][r] = b1.x; Bs[cc + 5][r] = b1.y; Bs[cc + 6][r] = b1.z; Bs[cc + 7][r] = b1.w;
        __syncthreads();
#pragma unroll
        for (int kv = 0; kv < 32; kv++) {
            float4 av = *(const float4*)&As[kv][ty * 4];
            float4 bv = *(const float4*)&Bs[kv][tx * 4];
            float a[4] = {av.x, av.y, av.z, av.w};
            float b[4] = {bv.x, bv.y, bv.z, bv.w};
#pragma unroll
            for (int i = 0; i < 4; i++)
#pragma unroll
                for (int j = 0; j < 4; j++) acc[i][j] += a[i] * b[j];
        }
    }
#pragma unroll
    for (int i = 0; i < 4; i++) {
        float4 o = make_float4(acc[i][0], acc[i][1], acc[i][2], acc[i][3]);
        *(float4*)&C[(size_t)(i0 + ty * 4 + i) * SEQ + l0 + tx * 4] = o;
    }
}

// ---------------- Phase 1b: U[l][d] = (1/(l+1)) sum_{i<=l} Pqk[i][l] Q[i][d]
__global__ void __launch_bounds__(256) k_U(const float* __restrict__ Q) {
    __shared__ float sh[128][8];
    const int tid = threadIdx.x;
    const int d = tid & 127, jh = tid >> 7;
    const int l0 = blockIdx.x * 8;
    float acc[4] = {0.f, 0.f, 0.f, 0.f};
    for (int i0 = 0; i0 <= l0 + 7; i0 += 128) {
        const int r = tid >> 1, c4 = (tid & 1) * 4;
        const int irow = i0 + r;
        float4 pv = *(const float4*)&g_Pqk[(size_t)irow * SEQ + l0 + c4];
        if (irow > l0 + c4 + 0) pv.x = 0.f;
        if (irow > l0 + c4 + 1) pv.y = 0.f;
        if (irow > l0 + c4 + 2) pv.z = 0.f;
        if (irow > l0 + c4 + 3) pv.w = 0.f;
        __syncthreads();
        *(float4*)&sh[r][c4] = pv;
        __syncthreads();
#pragma unroll 8
        for (int r2 = 0; r2 < 128; r2++) {
            float qv = Q[(size_t)(i0 + r2) * DK + d];
            float4 s4 = *(const float4*)&sh[r2][jh * 4];
            acc[0] += qv * s4.x; acc[1] += qv * s4.y;
            acc[2] += qv * s4.z; acc[3] += qv * s4.w;
        }
    }
#pragma unroll
    for (int jl = 0; jl < 4; jl++) {
        const int l = l0 + jh * 4 + jl;
        g_U[(size_t)l * DK + d] = acc[jl] / (float)(l + 1);
    }
}

// ---------------- Phase 1c: per-step scalars --------------------------------
__global__ void __launch_bounds__(256) k_scal() {
    const int tid = threadIdx.x;
    const int c = tid & 63;
    const int rq = tid >> 6;
    const int l0 = blockIdx.x * 64;
    const int l = l0 + c;
    float ss = 0.f, k2 = 0.f;
    const int ntiles = blockIdx.x + 1;
    for (int tt = 0; tt < ntiles; tt++) {
        const int ib = tt * 64 + rq * 16;
#pragma unroll 4
        for (int j = 0; j < 16; j++) {
            const int i = ib + j;
            if (i <= l) {
                float pq = g_Pqk[(size_t)i * SEQ + l];
                float pv = g_Pvv[(size_t)i * SEQ + l];
                ss += pq * pv;
                k2 += pq * pq;
            }
        }
    }
    __shared__ float rs[4][64], rk[4][64];
    rs[rq][c] = ss; rk[rq][c] = k2;
    __syncthreads();
    if (tid < 64) {
        float s  = rs[0][tid] + rs[1][tid] + rs[2][tid] + rs[3][tid];
        float kq = rk[0][tid] + rk[1][tid] + rk[2][tid] + rk[3][tid];
        const int ll = l0 + tid;
        const float fl = (float)(ll + 1);
        const float bm = 1.0f / fl;
        *(float4*)&g_chain[(size_t)ll * 12] =
            make_float4(s * bm, kq * bm, g_Pvv[(size_t)ll * SEQ + ll], bm);
        g_chain[(size_t)ll * 12 + 10] = (fl - 1.0f) * bm;
        g_chain[(size_t)ll * 12 + 11] = 0.f;
    }
}

// ---------------- Phase 1d: near-diagonal dots ------------------------------
// k1q=k_{l-1}.q_l  k2q=k_{l-2}.q_l  k1u=k_{l-1}.u_l  k2u=k_{l-2}.u_l
// vl1=v_{l-1}.v_l  vl2=v_{l-2}.v_l
__global__ void __launch_bounds__(128) k_adj(const float* __restrict__ q,
                                             const float* __restrict__ kk_,
                                             const float* __restrict__ v) {
    const int l = blockIdx.x, t = threadIdx.x;
    float s[6] = {0.f, 0.f, 0.f, 0.f, 0.f, 0.f};
    const float qv = q[(size_t)l * DK + t];
    const float uv = g_U[(size_t)l * DK + t];
    const float vv = v[(size_t)l * DK + t];
    if (l >= 1) {
        float k1 = kk_[(size_t)(l - 1) * DK + t];
        s[0] = k1 * qv; s[2] = k1 * uv;
        s[4] = v[(size_t)(l - 1) * DK + t] * vv;
    }
    if (l >= 2) {
        float k2 = kk_[(size_t)(l - 2) * DK + t];
        s[1] = k2 * qv; s[3] = k2 * uv;
        s[5] = v[(size_t)(l - 2) * DK + t] * vv;
    }
#pragma unroll
    for (int o = 16; o > 0; o >>= 1)
#pragma unroll
        for (int x = 0; x < 6; x++) s[x] += __shfl_down_sync(0xffffffffu, s[x], o);
    __shared__ float r[6][4];
    if ((t & 31) == 0)
#pragma unroll
        for (int x = 0; x < 6; x++) r[x][t >> 5] = s[x];
    __syncthreads();
    if (t == 0) {
        float f[6];
#pragma unroll
        for (int x = 0; x < 6; x++) f[x] = r[x][0] + r[x][1] + r[x][2] + r[x][3];
        *(float4*)&g_chain[(size_t)l * 12 + 4] = make_float4(f[0], f[1], f[2], f[3]);
        g_chain[(size_t)l * 12 + 8] = f[4];
        g_chain[(size_t)l * 12 + 9] = f[5];
    }
}

// ---------------- Phase 2: warp-specialized lag-3 recursion -----------------
// 576 threads = 16 compute warps (512) + 1 reduce warp + 1 chain warp.
// Schedule at iteration i:
//   compute: apply coeff(step i-3); matvec row i vs Jhat (upd thru i-3);
//            STS partials; stage row i+1 (regs prefetched depth-2)
//   reduce : part(row i-1) -> 5 sums (vs Jhat_{(i-1)-3})
//   chain  : step l=i-2 from sums(i-2), correcting 2 pending rank-1 updates
__global__ void __launch_bounds__(576, 1) k_seq(const float* __restrict__ q,
                                                const float* __restrict__ kg,
                                                const float* __restrict__ v,
                                                float* __restrict__ out) {
    __shared__ float  qsh[2][128], ush[2][128];
    __shared__ float  ksh[8][128], vsh[8][128];
    __shared__ float2 part[2][4][128];
    __shared__ float  wsumb[2][8];
    __shared__ float4 coeff[2];
    __shared__ float  sigf;

    const int tid = threadIdx.x;
    const bool is_compute = tid < 512;
    const bool is_reduce  = (tid >= 512 && tid < 544);

    // compute-role identifiers
    const int seg = tid >> 7;          // valid for compute role
    const int row = tid & 127;
    const float* src = (seg == 0) ? q : (seg == 1) ? kg : (seg == 2) ? v : g_U;

    unsigned long long Jp[16];
#pragma unroll
    for (int c = 0; c < 16; c++) Jp[c] = 0ull;

    // chain-role state
    float S = 0.f, T = 0.f, trS = 0.f;
    float sg1 = 1.f, sg2 = 1.f, sg3 = 1.f;   // sigma_{l-1}, sigma_{l-2}, sigma_{l-3}
    float c1 = 0.f, d1 = 0.f, c2 = 0.f, d2 = 0.f;
    float pvv1 = 0.f, pvv2 = 0.f, pvl1 = 0.f;
    float4 cA = {0,0,0,0}, cB = {0,0,0,0}, cC = {0,0,0,0};
    float4 nA = {0,0,0,0}, nB = {0,0,0,0}, nC = {0,0,0,0};

    // staging prefetch regs (compute role)
    float nx1 = 0.f, nx2 = 0.f;

    // ---- prologue ----
    if (tid < 128) {
#pragma unroll
        for (int s = 1; s < 8; s++) { ksh[s][tid] = 0.f; vsh[s][tid] = 0.f; }
    }
    if (tid == 0) {
        coeff[0] = make_float4(1.f, 0.f, 0.f, 0.f);
        coeff[1] = make_float4(1.f, 0.f, 0.f, 0.f);
#pragma unroll
        for (int j = 0; j < 8; j++) { wsumb[0][j] = 0.f; wsumb[1][j] = 0.f; }
        sigf = 1.f;
    }
    if (is_compute) {
        float x0 = src[row];
        if (seg == 0)      qsh[0][row] = x0;
        else if (seg == 1) ksh[0][row] = x0;
        else if (seg == 2) vsh[0][row] = x0;
        else               ush[0][row] = x0;
        nx1 = src[(size_t)1 * DK + row];
        nx2 = src[(size_t)2 * DK + row];
    } else if (tid == 544) {
        const float4* ch = (const float4*)g_chain;
        cA = ch[0]; cB = ch[1]; cC = ch[2];      // row 0 (12 floats = 3 float4)
        nA = ch[3]; nB = ch[4]; nC = ch[5];      // row 1
    }
    __syncthreads();

    // ---- main loop ----
    for (int i = 0; i <= SEQ + 2; i++) {
        if (is_compute) {
            // (a) apply published update for step i-3
            if (i >= 3) {
                float4 cc = coeff[(i - 3) & 1];
                if (cc.x != 1.f || cc.y != 0.f) {
                    const int s3 = (i - 3) & 7;
                    const float bv = cc.y * vsh[s3][row];
                    const unsigned long long bvp = pk2(bv, bv);
                    const ulonglong2* kp = (const ulonglong2*)&ksh[s3][seg * 32];
                    if (cc.x == 1.f) {
#pragma unroll
                        for (int c = 0; c < 8; c++) {
                            ulonglong2 kv = kp[c];
                            Jp[2 * c + 0] = ffma2(kv.x, bvp, Jp[2 * c + 0]);
                            Jp[2 * c + 1] = ffma2(kv.y, bvp, Jp[2 * c + 1]);
                        }
                    } else {
                        const unsigned long long mp = pk2(cc.x, cc.x);
#pragma unroll
                        for (int c = 0; c < 8; c++) {
                            ulonglong2 kv = kp[c];
                            Jp[2 * c + 0] = ffma2(kv.x, bvp, fmul2(Jp[2 * c + 0], mp));
                            Jp[2 * c + 1] = ffma2(kv.y, bvp, fmul2(Jp[2 * c + 1], mp));
                        }
                    }
                }
            }
            // (b) matvec row i
            if (i < SEQ) {
                unsigned long long a1a = 0ull, a1b = 0ull, a2a = 0ull, a2b = 0ull;
                const ulonglong2* qp = (const ulonglong2*)&qsh[i & 1][seg * 32];
                const ulonglong2* up = (const ulonglong2*)&ush[i & 1][seg * 32];
#pragma unroll
                for (int c2 = 0; c2 < 4; c2++) {
                    ulonglong2 q0 = qp[2 * c2], q1 = qp[2 * c2 + 1];
                    ulonglong2 u0 = up[2 * c2], u1 = up[2 * c2 + 1];
                    a1a = ffma2(Jp[4 * c2 + 0], q0.x, a1a);
                    a1b = ffma2(Jp[4 * c2 + 1], q0.y, a1b);
                    a1a = ffma2(Jp[4 * c2 + 2], q1.x, a1a);
                    a1b = ffma2(Jp[4 * c2 + 3], q1.y, a1b);
                    a2a = ffma2(Jp[4 * c2 + 0], u0.x, a2a);
                    a2b = ffma2(Jp[4 * c2 + 1], u0.y, a2b);
                    a2a = ffma2(Jp[4 * c2 + 2], u1.x, a2a);
                    a2b = ffma2(Jp[4 * c2 + 3], u1.y, a2b);
                }
                float2 f1a = upk2(a1a), f1b = upk2(a1b);
                float2 f2a = upk2(a2a), f2b = upk2(a2b);
                part[i & 1][seg][row] =
                    make_float2((f1a.x + f1a.y) + (f1b.x + f1b.y),
                                (f2a.x + f2a.y) + (f2b.x + f2b.y));
            }
            // (c) stage row i+1 (from reg), prefetch row i+3
            if (i + 1 < SEQ) {
                if (seg == 0)      qsh[(i + 1) & 1][row] = nx1;
                else if (seg == 1) ksh[(i + 1) & 7][row] = nx1;
                else if (seg == 2) vsh[(i + 1) & 7][row] = nx1;
                else               ush[(i + 1) & 1][row] = nx1;
            }
            nx1 = nx2;
            nx2 = (i + 3 < SEQ) ? src[(size_t)(i + 3) * DK + row] : 0.f;
        } else if (is_reduce) {
            const int r = i - 1;
            if (r >= 0 && r < SEQ) {
                const int j = tid & 31;
                const int buf = r & 1, s0 = r & 7, s1 = (r - 1) & 7, s2 = (r - 2) & 7;
                float x1 = 0.f, x2 = 0.f, x3 = 0.f, x4 = 0.f, x5 = 0.f;
#pragma unroll
                for (int rr4 = 0; rr4 < 4; rr4++) {
                    const int rr = j + rr4 * 32;
                    float2 p0 = part[buf][0][rr], p1 = part[buf][1][rr];
                    float2 p2 = part[buf][2][rr], p3 = part[buf][3][rr];
                    float a = p0.x + p1.x + p2.x + p3.x;
                    float b = p0.y + p1.y + p2.y + p3.y;
                    float vl = vsh[s0][rr], vm1 = vsh[s1][rr], vm2 = vsh[s2][rr];
                    x1 += vl * a; x2 += a * a; x3 += vl * b;
                    x4 += vm1 * a; x5 += vm2 * a;
                }
#pragma unroll
                for (int o = 16; o > 0; o >>= 1) {
                    x1 += __shfl_down_sync(0xffffffffu, x1, o);
                    x2 += __shfl_down_sync(0xffffffffu, x2, o);
                    x3 += __shfl_down_sync(0xffffffffu, x3, o);
                    x4 += __shfl_down_sync(0xffffffffu, x4, o);
                    x5 += __shfl_down_sync(0xffffffffu, x5, o);
                }
                if (j == 0) {
                    wsumb[buf][0] = x1; wsumb[buf][1] = x2; wsumb[buf][2] = x3;
                    wsumb[buf][3] = x4; wsumb[buf][4] = x5;
                }
            }
        } else if (tid == 544) {
            const int l = i - 2;
            if (l >= 0 && l < SEQ) {
                const int wb = l & 1;
                const float B1 = wsumb[wb][0], B2 = wsumb[wb][1], B3 = wsumb[wb][2];
                const float B4 = wsumb[wb][3], B5 = wsumb[wb][4];
                const float s_l = cA.x, kqq = cA.y, vv = cA.z, bm = cA.w;
                const float k1q = cB.x, k2q = cB.y, k1u = cB.z, k2u = cB.w;
                const float vl1 = cC.x, vl2 = cC.y, am = cC.z;

                const float A   = c1 * c2 * sg3;
                const float C2c = c1 * d2;
                const float C1c = d1;
                const float X1 = A * B1 + C2c * vl2 * k2q + C1c * vl1 * k1q;
                const float X3 = A * B3 + C2c * vl2 * k2u + C1c * vl1 * k1u;
                const float X2 = A * A * B2
                               + C2c * C2c * k2q * k2q * pvv2
                               + C1c * C1c * k1q * k1q * pvv1
                               + 2.f * A * (C2c * k2q * B5 + C1c * k1q * B4)
                               + 2.f * C2c * C1c * k2q * k1q * pvl1;

                trS = am * trS + vv * bm;
                const float sJ   = am * S + bm * X1;
                const float A_JJ = am * T + bm * X2;
                const float A_Jl = X3;
                const float A_ll = vv * kqq;

                const bool first = (l == 0);
                const float A_JJ_s = (first || A_JJ == 0.f) ? 1.f : A_JJ;
                const float A_ll_s = (first || A_ll == 0.f) ? 1.f : A_ll;
                const float denom  = A_JJ * A_ll - A_Jl * A_Jl;
                const float denom_s = (first || denom == 0.f) ? 1.f : denom;

                const float margin = s_l - A_Jl * __fdividef(sJ, A_JJ_s);
                const float rden = __fdividef(1.f, denom_s);
                const float wf = (A_ll * sJ - A_Jl * s_l) * rden;
                const float wi = (A_JJ * s_l - A_Jl * sJ) * rden;
                const float wf_c = (wi <= 0.f) ? __fdividef(sJ, A_JJ_s)
                                               : ((wf <= 0.f) ? 0.f : wf);
                const float wi_c = (wi <= 0.f) ? 0.f
                                               : ((wf <= 0.f) ? __fdividef(s_l, A_ll_s) : wi);
                const bool do_upd = margin > 0.f;

                float cf, ci, upd;
                if (first)       { cf = 0.f;  ci = 1.f;  upd = 1.f; S = s_l; T = A_ll; }
                else if (do_upd) { cf = wf_c; ci = wi_c; upd = 1.f;
                                   S = cf * sJ + ci * s_l;
                                   T = cf * cf * A_JJ + 2.f * cf * ci * A_Jl + ci * ci * A_ll; }
                else             { cf = 1.f;  ci = 0.f;  upd = 0.f; S = sJ; T = A_JJ; }

                out[l] = 0.5f * trS - S + 0.5f * T;
                out[SEQ + l] = upd;

                // publish normalized coeffs (m, beta) and track sigma
                float m, beta, signew;
                if (!(first || do_upd)) { m = 1.f; beta = 0.f; signew = sg1; }
                else {
                    const float s2v = sg1 * cf;
                    if (cf == 0.f)  { m = 0.f; beta = ci; signew = 1.f; }
                    else if (fabsf(s2v) < 1e-12f || fabsf(s2v) > 1e12f)
                                    { m = s2v; beta = ci; signew = 1.f; }
                    else            { m = 1.f; beta = __fdividef(ci, s2v); signew = s2v; }
                }
                coeff[wb] = make_float4(m, beta, 0.f, 0.f);
                if (l == SEQ - 1) sigf = signew;

                // rotate rings
                c2 = c1; d2 = d1; c1 = cf; d1 = ci;
                sg3 = sg2; sg2 = sg1; sg1 = signew;
                pvv2 = pvv1; pvv1 = vv; pvl1 = vl1;
                cA = nA; cB = nB; cC = nC;
                if (l + 2 < SEQ) {
                    const float4* ch = (const float4*)&g_chain[(size_t)(l + 2) * 12];
                    nA = ch[0]; nB = ch[1]; nC = ch[2];
                }
            }
        }
        __syncthreads();
    }

    // ---- epilogue: write final J = sigf * Jhat ----
    if (is_compute) {
        const float sf = sigf;
#pragma unroll
        for (int c = 0; c < 16; c++) {
            float2 jf = upk2(Jp[c]);
            out[2 * SEQ + (size_t)row * DK + seg * 32 + 2 * c + 0] = sf * jf.x;
            out[2 * SEQ + (size_t)row * DK + seg * 32 + 2 * c + 1] = sf * jf.y;
        }
    }
}

// ---------------------------------------------------------------------------
extern "C" void kernel_launch(void* const* d_in, const int* in_sizes, int n_in,
                              void* d_out, int out_size) {
    const float* q = (const float*)d_in[0];
    const float* k = (const float*)d_in[1];
    const float* v = (const float*)d_in[2];
    float* out = (float*)d_out;

    dim3 gg(SEQ / 64, SEQ / 64, 2);
    k_gemm<<<gg, 256>>>(q, k, v);
    k_U<<<SEQ / 8, 256>>>(q);
    k_scal<<<SEQ / 64, 256>>>();
    k_adj<<<SEQ, 128>>>(q, k, v);
    k_seq<<<1, 576>>>(q, k, v, out);
    (void)in_sizes; (void)n_in; (void)out_size;
}

// round 6
// speedup vs baseline: 1.3559x; 1.3559x over previous
#include <cuda_runtime.h>
#include <cstdint>

#define SEQ 2048
#define DK  128

// ---------------- static device scratch (no allocations allowed) ------------
__device__ float g_Pqk[(size_t)SEQ * SEQ];   // P_qk[i][l] = q_i . k_l
__device__ float g_Pvv[(size_t)SEQ * SEQ];   // P_vv[i][l] = v_i . v_l
__device__ float g_U[(size_t)SEQ * DK];      // u_l = Sqq_l k_l (incl 1/(l+1))
// per-step chain constants, 8 floats per step:
// [0..3]={s_l, kqq_l, vv_l, 0}  [4..7]={k1q, k1u, vvm, 0}
__device__ float g_chain[(size_t)SEQ * 8];

// ---------------- f32x2 packed helpers (sm_103a) ----------------------------
__device__ __forceinline__ unsigned long long ffma2(unsigned long long a,
                                                    unsigned long long b,
                                                    unsigned long long c) {
    unsigned long long d;
    asm("fma.rn.f32x2 %0, %1, %2, %3;" : "=l"(d) : "l"(a), "l"(b), "l"(c));
    return d;
}
__device__ __forceinline__ unsigned long long fmul2(unsigned long long a,
                                                    unsigned long long b) {
    unsigned long long d;
    asm("mul.rn.f32x2 %0, %1, %2;" : "=l"(d) : "l"(a), "l"(b));
    return d;
}
__device__ __forceinline__ unsigned long long pk2(float lo, float hi) {
    unsigned long long r;
    asm("mov.b64 %0, {%1, %2};" : "=l"(r) : "f"(lo), "f"(hi));
    return r;
}
__device__ __forceinline__ float2 upk2(unsigned long long a) {
    float2 f;
    asm("mov.b64 {%0, %1}, %2;" : "=f"(f.x), "=f"(f.y) : "l"(a));
    return f;
}

// ---------------- Phase 1a: both Gram matrices in one launch ----------------
__global__ void __launch_bounds__(256) k_gemm(const float* __restrict__ q,
                                              const float* __restrict__ kk_,
                                              const float* __restrict__ v) {
    if (blockIdx.y > blockIdx.x) return;
    const float* A; const float* B; float* C;
    if (blockIdx.z == 0) { A = q; B = kk_; C = g_Pqk; }
    else                 { A = v; B = v;   C = g_Pvv; }
    __shared__ float As[32][68];
    __shared__ float Bs[32][68];
    const int tx = threadIdx.x & 15, ty = threadIdx.x >> 4;
    const int i0 = blockIdx.y * 64, l0 = blockIdx.x * 64;
    const int t = threadIdx.x;
    const int r = t >> 2, cc = (t & 3) * 8;
    float acc[4][4] = {};
    for (int k0 = 0; k0 < DK; k0 += 32) {
        float4 a0 = *(const float4*)&A[(size_t)(i0 + r) * DK + k0 + cc];
        float4 a1 = *(const float4*)&A[(size_t)(i0 + r) * DK + k0 + cc + 4];
        float4 b0 = *(const float4*)&B[(size_t)(l0 + r) * DK + k0 + cc];
        float4 b1 = *(const float4*)&B[(size_t)(l0 + r) * DK + k0 + cc + 4];
        __syncthreads();
        As[cc + 0][r] = a0.x; As[cc + 1][r] = a0.y; As[cc + 2][r] = a0.z; As[cc + 3][r] = a0.w;
        As[cc + 4][r] = a1.x; As[cc + 5][r] = a1.y; As[cc + 6][r] = a1.z; As[cc + 7][r] = a1.w;
        Bs[cc + 0][r] = b0.x; Bs[cc + 1][r] = b0.y; Bs[cc + 2][r] = b0.z; Bs[cc + 3][r] = b0.w;
        Bs[cc + 4][r] = b1.x; Bs[cc + 5][r] = b1.y; Bs[cc + 6][r] = b1.z; Bs[cc + 7][r] = b1.w;
        __syncthreads();
#pragma unroll
        for (int kv = 0; kv < 32; kv++) {
            float4 av = *(const float4*)&As[kv][ty * 4];
            float4 bv = *(const float4*)&Bs[kv][tx * 4];
            float a[4] = {av.x, av.y, av.z, av.w};
            float b[4] = {bv.x, bv.y, bv.z, bv.w};
#pragma unroll
            for (int i = 0; i < 4; i++)
#pragma unroll
                for (int j = 0; j < 4; j++) acc[i][j] += a[i] * b[j];
        }
    }
#pragma unroll
    for (int i = 0; i < 4; i++) {
        float4 o = make_float4(acc[i][0], acc[i][1], acc[i][2], acc[i][3]);
        *(float4*)&C[(size_t)(i0 + ty * 4 + i) * SEQ + l0 + tx * 4] = o;
    }
}

// ---------------- Phase 1b: U + k1u dot -------------------------------------
// U[l][d] = (1/(l+1)) sum_{i<=l} Pqk[i][l] Q[i][d]; k1u_l = k_{l-1}.u_l
__global__ void __launch_bounds__(256) k_U(const float* __restrict__ Q,
                                           const float* __restrict__ KK) {
    __shared__ float sh[128][8];
    __shared__ float red[8][4];
    const int tid = threadIdx.x;
    const int d = tid & 127, jh = tid >> 7;
    const int l0 = blockIdx.x * 8;
    float acc[4] = {0.f, 0.f, 0.f, 0.f};
    for (int i0 = 0; i0 <= l0 + 7; i0 += 128) {
        const int r = tid >> 1, c4 = (tid & 1) * 4;
        const int irow = i0 + r;
        float4 pv = *(const float4*)&g_Pqk[(size_t)irow * SEQ + l0 + c4];
        if (irow > l0 + c4 + 0) pv.x = 0.f;
        if (irow > l0 + c4 + 1) pv.y = 0.f;
        if (irow > l0 + c4 + 2) pv.z = 0.f;
        if (irow > l0 + c4 + 3) pv.w = 0.f;
        __syncthreads();
        *(float4*)&sh[r][c4] = pv;
        __syncthreads();
#pragma unroll 8
        for (int r2 = 0; r2 < 128; r2++) {
            float qv = Q[(size_t)(i0 + r2) * DK + d];
            float4 s4 = *(const float4*)&sh[r2][jh * 4];
            acc[0] += qv * s4.x; acc[1] += qv * s4.y;
            acc[2] += qv * s4.z; acc[3] += qv * s4.w;
        }
    }
    float uval[4];
#pragma unroll
    for (int jl = 0; jl < 4; jl++) {
        const int l = l0 + jh * 4 + jl;
        uval[jl] = acc[jl] / (float)(l + 1);
        g_U[(size_t)l * DK + d] = uval[jl];
    }
    // k1u = k_{l-1} . u_l  (reduce over the 128 threads of this jh half)
#pragma unroll
    for (int jl = 0; jl < 4; jl++) {
        const int l = l0 + jh * 4 + jl;
        float p = (l >= 1) ? uval[jl] * KK[(size_t)(l - 1) * DK + d] : 0.f;
#pragma unroll
        for (int o = 16; o > 0; o >>= 1)
            p += __shfl_down_sync(0xffffffffu, p, o);
        if ((tid & 31) == 0) red[tid >> 5][jl] = p;
    }
    __syncthreads();
    if (tid < 8) {
        const int jh2 = tid >> 2, jl2 = tid & 3;
        const int l = l0 + jh2 * 4 + jl2;
        const int w0 = jh2 * 4;
        g_chain[(size_t)l * 8 + 5] =
            red[w0][jl2] + red[w0 + 1][jl2] + red[w0 + 2][jl2] + red[w0 + 3][jl2];
    }
}

// ---------------- Phase 1c: per-step scalars + near dots --------------------
__global__ void __launch_bounds__(256) k_scal(const float* __restrict__ q,
                                              const float* __restrict__ kk_,
                                              const float* __restrict__ v) {
    const int tid = threadIdx.x;
    const int c = tid & 63;
    const int rq = tid >> 6;
    const int l0 = blockIdx.x * 64;
    const int l = l0 + c;
    float ss = 0.f, k2 = 0.f;
    const int ntiles = blockIdx.x + 1;
    for (int tt = 0; tt < ntiles; tt++) {
        const int ib = tt * 64 + rq * 16;
#pragma unroll 4
        for (int j = 0; j < 16; j++) {
            const int i = ib + j;
            if (i <= l) {
                float pq = g_Pqk[(size_t)i * SEQ + l];
                float pv = g_Pvv[(size_t)i * SEQ + l];
                ss += pq * pv;
                k2 += pq * pq;
            }
        }
    }
    __shared__ float rs[4][64], rk[4][64];
    rs[rq][c] = ss; rk[rq][c] = k2;
    __syncthreads();
    if (tid < 64) {
        float s  = rs[0][tid] + rs[1][tid] + rs[2][tid] + rs[3][tid];
        float kq = rk[0][tid] + rk[1][tid] + rk[2][tid] + rk[3][tid];
        const int ll = l0 + tid;
        const float fl = (float)(ll + 1);
        const float bm = 1.0f / fl;
        *(float4*)&g_chain[(size_t)ll * 8] =
            make_float4(s * bm, kq * bm, g_Pvv[(size_t)ll * SEQ + ll], 0.f);
    }
    // near dots: k1q = k_{l-1}.q_l ; vvm = v_{l-1}.v_l  (4 threads per column)
    const int lc = tid >> 2, td = tid & 3;
    const int ln = l0 + lc;
    float akq = 0.f, avv = 0.f;
    if (ln >= 1) {
        const float4* qp = (const float4*)&q[(size_t)ln * DK + td * 32];
        const float4* kp = (const float4*)&kk_[(size_t)(ln - 1) * DK + td * 32];
        const float4* vp = (const float4*)&v[(size_t)ln * DK + td * 32];
        const float4* wp = (const float4*)&v[(size_t)(ln - 1) * DK + td * 32];
#pragma unroll
        for (int x = 0; x < 8; x++) {
            float4 a = kp[x], b = qp[x], cv = wp[x], dv = vp[x];
            akq += a.x * b.x + a.y * b.y + a.z * b.z + a.w * b.w;
            avv += cv.x * dv.x + cv.y * dv.y + cv.z * dv.z + cv.w * dv.w;
        }
    }
    akq += __shfl_down_sync(0xffffffffu, akq, 2);
    akq += __shfl_down_sync(0xffffffffu, akq, 1);
    avv += __shfl_down_sync(0xffffffffu, avv, 2);
    avv += __shfl_down_sync(0xffffffffu, avv, 1);
    if (td == 0) {
        g_chain[(size_t)ln * 8 + 4] = akq;
        g_chain[(size_t)ln * 8 + 6] = avv;
        g_chain[(size_t)ln * 8 + 7] = 0.f;
    }
}

// ---------------- Phase 2: pipelined sequential recursion (R3 skeleton) -----
// 512 threads, seg=tid>>7, row=tid&127; J[row][seg*32..+32) in 16 x f32x2 regs.
// Lag-2 pipeline: iter i does matvec of row i vs Jhat_{i-2}; warps 1-4 reduce
// row i after a named barrier; warp 0 runs the scalar chain for step i-1
// concurrently, correcting for the single pending rank-1 update.
__global__ void __launch_bounds__(512) k_seq(const float* __restrict__ q,
                                             const float* __restrict__ kg,
                                             const float* __restrict__ v,
                                             float* __restrict__ out) {
    // unified vector buffer: q ring2 [0,256) | k ring4 [256,768)
    //                      | v ring4 [768,1280) | u ring2 [1280,1536)
    __shared__ float  vbuf[1536];
    __shared__ float2 part[512];
    __shared__ float4 wsumb[2][4];
    __shared__ float4 coeff[2];
    __shared__ float  sigf;

    const int tid = threadIdx.x;
    const int seg = tid >> 7;
    const int row = tid & 127;

    const int stg_base = (seg == 0) ? 0 : (seg == 1) ? 256 : (seg == 2) ? 768 : 1280;
    const int rmask = (seg == 1 || seg == 2) ? 3 : 1;
    const float* src = (seg == 0) ? q : (seg == 1) ? kg : (seg == 2) ? v : g_U;

    unsigned long long Jp[16];
#pragma unroll
    for (int c = 0; c < 16; c++) Jp[c] = 0ull;

    // chain-role state (warp 0)
    float S = 0.f, T = 0.f, trS = 0.f;
    float sig_m = 1.f, sig_p = 1.f;
    float cp = 0.f, dp = 0.f, vvprev = 0.f;
    float4 pA = {0, 0, 0, 0}, pB = {0, 0, 0, 0};
    float4 nA = {0, 0, 0, 0}, nB = {0, 0, 0, 0};

    // zero rings, init coeffs
    vbuf[tid] = 0.f; vbuf[tid + 512] = 0.f; vbuf[tid + 1024] = 0.f;
    if (tid == 0) {
        coeff[0] = make_float4(1.f, 0.f, 0.f, 0.f);
        coeff[1] = make_float4(1.f, 0.f, 0.f, 0.f);
        sigf = 1.f;
    }
    __syncthreads();
    // stage row 0, prefetch rows 1,2
    vbuf[stg_base + row] = src[row];
    float nx1 = src[(size_t)1 * DK + row];
    float nx2 = src[(size_t)2 * DK + row];
    if (tid < 32) {
        const float4* ch = (const float4*)g_chain;
        pA = ch[0]; pB = ch[1];
        nA = ch[2]; nB = ch[3];
    }
    __syncthreads();

#pragma unroll 2
    for (int i = 0; i <= SEQ; i++) {
        const int par = i & 1;

        // ---- (a) apply published update for step i-2 ------------------------
        {
            float4 cc = coeff[par];
            if (cc.x != 1.f || cc.y != 0.f) {
                const int s2 = (i - 2) & 3;
                const float bv = cc.y * vbuf[768 + s2 * 128 + row];
                const unsigned long long bvp = pk2(bv, bv);
                const ulonglong2* kp = (const ulonglong2*)&vbuf[256 + s2 * 128 + seg * 32];
                if (cc.x == 1.f) {
#pragma unroll
                    for (int c = 0; c < 8; c++) {
                        ulonglong2 kv = kp[c];
                        Jp[2 * c + 0] = ffma2(kv.x, bvp, Jp[2 * c + 0]);
                        Jp[2 * c + 1] = ffma2(kv.y, bvp, Jp[2 * c + 1]);
                    }
                } else {
                    const unsigned long long mp = pk2(cc.x, cc.x);
#pragma unroll
                    for (int c = 0; c < 8; c++) {
                        ulonglong2 kv = kp[c];
                        Jp[2 * c + 0] = ffma2(kv.x, bvp, fmul2(Jp[2 * c + 0], mp));
                        Jp[2 * c + 1] = ffma2(kv.y, bvp, fmul2(Jp[2 * c + 1], mp));
                    }
                }
            }
        }

        // ---- (b) matvec row i vs Jhat --------------------------------------
        if (i < SEQ) {
            unsigned long long a1a = 0ull, a1b = 0ull, a2a = 0ull, a2b = 0ull;
            const ulonglong2* qp = (const ulonglong2*)&vbuf[par * 128 + seg * 32];
            const ulonglong2* up = (const ulonglong2*)&vbuf[1280 + par * 128 + seg * 32];
#pragma unroll
            for (int c2 = 0; c2 < 4; c2++) {
                ulonglong2 q0 = qp[2 * c2], q1 = qp[2 * c2 + 1];
                ulonglong2 u0 = up[2 * c2], u1 = up[2 * c2 + 1];
                a1a = ffma2(Jp[4 * c2 + 0], q0.x, a1a);
                a1b = ffma2(Jp[4 * c2 + 1], q0.y, a1b);
                a1a = ffma2(Jp[4 * c2 + 2], q1.x, a1a);
                a1b = ffma2(Jp[4 * c2 + 3], q1.y, a1b);
                a2a = ffma2(Jp[4 * c2 + 0], u0.x, a2a);
                a2b = ffma2(Jp[4 * c2 + 1], u0.y, a2b);
                a2a = ffma2(Jp[4 * c2 + 2], u1.x, a2a);
                a2b = ffma2(Jp[4 * c2 + 3], u1.y, a2b);
            }
            float2 f1a = upk2(a1a), f1b = upk2(a1b);
            float2 f2a = upk2(a2a), f2b = upk2(a2b);
            part[tid] = make_float2((f1a.x + f1a.y) + (f1b.x + f1b.y),
                                    (f2a.x + f2a.y) + (f2b.x + f2b.y));
        }

        // ---- (c) stage row i+1 (depth-2 prefetched), rotate ----------------
        if (i + 1 < SEQ)
            vbuf[stg_base + ((i + 1) & rmask) * 128 + row] = nx1;
        nx1 = nx2;
        nx2 = (i + 3 < SEQ) ? src[(size_t)(i + 3) * DK + row] : 0.f;

        // ---- (d) split barrier + roles -------------------------------------
        if (tid >= 32 && tid < 160) {
            asm volatile("bar.sync 1, 512;" ::: "memory");
            if (i < SEQ) {
                const int j = tid - 32;
                float2 p0 = part[j], pa = part[j + 128];
                float2 pb = part[j + 256], pc = part[j + 384];
                float a = p0.x + pa.x + pb.x + pc.x;
                float b = p0.y + pa.y + pb.y + pc.y;
                float vl = vbuf[768 + (i & 3) * 128 + j];
                float vm = vbuf[768 + ((i + 3) & 3) * 128 + j];
                float x1 = vl * a, x2 = a * a, x3 = vl * b, x4 = vm * a;
#pragma unroll
                for (int o = 16; o > 0; o >>= 1) {
                    x1 += __shfl_down_sync(0xffffffffu, x1, o);
                    x2 += __shfl_down_sync(0xffffffffu, x2, o);
                    x3 += __shfl_down_sync(0xffffffffu, x3, o);
                    x4 += __shfl_down_sync(0xffffffffu, x4, o);
                }
                if ((tid & 31) == 0)
                    wsumb[par][(tid >> 5) - 1] = make_float4(x1, x2, x3, x4);
            }
        } else {
            asm volatile("bar.arrive 1, 512;" ::: "memory");
            if (tid < 32 && i > 0) {
                const int l = i - 1;
                float4 w0 = wsumb[1 - par][0], w1 = wsumb[1 - par][1];
                float4 w2 = wsumb[1 - par][2], w3 = wsumb[1 - par][3];
                const float B1 = w0.x + w1.x + w2.x + w3.x;
                const float B2 = w0.y + w1.y + w2.y + w3.y;
                const float B3 = w0.z + w1.z + w2.z + w3.z;
                const float B4 = w0.w + w1.w + w2.w + w3.w;

                const float s_l = pA.x, kqq = pA.y, vvl = pA.z;
                const float kq = pB.x, ku = pB.y, vvm = pB.z;

                const float c2s = cp * sig_m;
                const float X1 = c2s * B1 + dp * kq * vvm;
                const float X3 = c2s * B3 + dp * ku * vvm;
                const float X2 = c2s * c2s * B2 + 2.f * c2s * dp * kq * B4
                               + dp * dp * kq * kq * vvprev;

                const float fl = (float)(l + 1);
                const float bmv = __fdividef(1.f, fl);
                const float amv = (fl - 1.f) * bmv;
                trS = amv * trS + vvl * bmv;
                const float sJ   = amv * S + bmv * X1;
                const float A_JJ = amv * T + bmv * X2;
                const float A_Jl = X3;
                const float A_ll = vvl * kqq;

                const bool first = (l == 0);
                const float A_JJ_s = (first || A_JJ == 0.f) ? 1.f : A_JJ;
                const float A_ll_s = (first || A_ll == 0.f) ? 1.f : A_ll;
                const float denom  = A_JJ * A_ll - A_Jl * A_Jl;
                const float denom_s = (first || denom == 0.f) ? 1.f : denom;

                const float margin = s_l - A_Jl * __fdividef(sJ, A_JJ_s);
                const float rden = __fdividef(1.f, denom_s);
                const float wf = (A_ll * sJ - A_Jl * s_l) * rden;
                const float wi = (A_JJ * s_l - A_Jl * sJ) * rden;
                const float wf_c = (wi <= 0.f) ? __fdividef(sJ, A_JJ_s)
                                               : ((wf <= 0.f) ? 0.f : wf);
                const float wi_c = (wi <= 0.f) ? 0.f
                                               : ((wf <= 0.f) ? __fdividef(s_l, A_ll_s) : wi);
                const bool do_upd = margin > 0.f;

                float cf, ci, upd;
                if (first)       { cf = 0.f;  ci = 1.f;  upd = 1.f; S = s_l; T = A_ll; }
                else if (do_upd) { cf = wf_c; ci = wi_c; upd = 1.f;
                                   S = cf * sJ + ci * s_l;
                                   T = cf * cf * A_JJ + 2.f * cf * ci * A_Jl + ci * ci * A_ll; }
                else             { cf = 1.f;  ci = 0.f;  upd = 0.f; S = sJ; T = A_JJ; }

                if ((tid & 31) == 0) {
                    out[l] = 0.5f * trS - S + 0.5f * T;
                    out[SEQ + l] = upd;
                }

                float m, beta, signew;
                if (!(first || do_upd)) { m = 1.f; beta = 0.f; signew = sig_p; }
                else {
                    const float s2v = sig_p * cf;
                    if (cf == 0.f)  { m = 0.f; beta = ci; signew = 1.f; }
                    else if (fabsf(s2v) < 1e-12f || fabsf(s2v) > 1e12f)
                                    { m = s2v; beta = ci; signew = 1.f; }
                    else            { m = 1.f; beta = __fdividef(ci, s2v); signew = s2v; }
                }
                if ((tid & 31) == 0) {
                    coeff[1 - par] = make_float4(m, beta, 0.f, 0.f);
                    if (i == SEQ) sigf = signew;
                }
                sig_m = sig_p; sig_p = signew;
                cp = cf; dp = ci; vvprev = vvl;
                pA = nA; pB = nB;
                if (l + 2 < SEQ) {
                    const float4* ch = (const float4*)&g_chain[(size_t)(l + 2) * 8];
                    nA = ch[0]; nB = ch[1];
                }
            }
        }
        __syncthreads();
    }

    // ---- epilogue: apply final update (step SEQ-1), write J = sigf*Jhat ----
    {
        float4 cc = coeff[1];
        if (cc.x != 1.f || cc.y != 0.f) {
            const int s2 = (SEQ - 1) & 3;
            const float bv = cc.y * vbuf[768 + s2 * 128 + row];
            const unsigned long long bvp = pk2(bv, bv);
            const ulonglong2* kp = (const ulonglong2*)&vbuf[256 + s2 * 128 + seg * 32];
            if (cc.x == 1.f) {
#pragma unroll
                for (int c = 0; c < 8; c++) {
                    ulonglong2 kv = kp[c];
                    Jp[2 * c + 0] = ffma2(kv.x, bvp, Jp[2 * c + 0]);
                    Jp[2 * c + 1] = ffma2(kv.y, bvp, Jp[2 * c + 1]);
                }
            } else {
                const unsigned long long mp = pk2(cc.x, cc.x);
#pragma unroll
                for (int c = 0; c < 8; c++) {
                    ulonglong2 kv = kp[c];
                    Jp[2 * c + 0] = ffma2(kv.x, bvp, fmul2(Jp[2 * c + 0], mp));
                    Jp[2 * c + 1] = ffma2(kv.y, bvp, fmul2(Jp[2 * c + 1], mp));
                }
            }
        }
    }
    const float sf = sigf;
#pragma unroll
    for (int c = 0; c < 16; c++) {
        float2 jf = upk2(Jp[c]);
        out[2 * SEQ + (size_t)row * DK + seg * 32 + 2 * c + 0] = sf * jf.x;
        out[2 * SEQ + (size_t)row * DK + seg * 32 + 2 * c + 1] = sf * jf.y;
    }
}

// ---------------------------------------------------------------------------
extern "C" void kernel_launch(void* const* d_in, const int* in_sizes, int n_in,
                              void* d_out, int out_size) {
    const float* q = (const float*)d_in[0];
    const float* k = (const float*)d_in[1];
    const float* v = (const float*)d_in[2];
    float* out = (float*)d_out;

    dim3 gg(SEQ / 64, SEQ / 64, 2);
    k_gemm<<<gg, 256>>>(q, k, v);        // launch 0
    k_U<<<SEQ / 8, 256>>>(q, k);         // launch 1 (+ k1u dots)
    k_scal<<<SEQ / 64, 256>>>(q, k, v);  // launch 2 (+ k1q, vvm dots)
    k_seq<<<1, 512>>>(q, k, v, out);     // launch 3  <-- ncu capture slot
    (void)in_sizes; (void)n_in; (void)out_size;
}